// round 8
// baseline (speedup 1.0000x reference)
#include <cuda_runtime.h>
#include <math.h>

#define H 128
#define E_MAX 80000
#define N_MAX 40000

// ---------------- scratch (device globals; no allocation allowed) ----------
__device__ __align__(16) float g_Pz [E_MAX * H];
__device__ __align__(16) float g_Pr [E_MAX * H];
__device__ __align__(16) float g_Ph [E_MAX * H];
__device__ __align__(16) float g_q1 [E_MAX * H];
__device__ __align__(16) float g_q2 [E_MAX * H];
__device__ __align__(16) float g_hA [E_MAX * H];
__device__ __align__(16) float g_hB [E_MAX * H];
__device__ int g_bg32[E_MAX * 6];
__device__ int g_ag32[N_MAX * 6];
__device__ int g_idx_is64;

__device__ __forceinline__ float sigmoidf_(float x) { return 1.0f / (1.0f + expf(-x)); }
__device__ __forceinline__ unsigned f2tf32(float f) {
    unsigned u; asm("cvt.rna.tf32.f32 %0, %1;" : "=r"(u) : "f"(f)); return u;
}
__device__ __forceinline__ float ftf32(float f) {
    unsigned u; asm("cvt.rna.tf32.f32 %0, %1;" : "=r"(u) : "f"(f));
    return __uint_as_float(u);
}

#define MMA_TF32(C, a, b) \
    asm volatile("mma.sync.aligned.m16n8k8.row.col.f32.tf32.tf32.f32 " \
        "{%0,%1,%2,%3},{%4,%5,%6,%7},{%8,%9},{%0,%1,%2,%3};" \
        : "+f"((C)[0]), "+f"((C)[1]), "+f"((C)[2]), "+f"((C)[3]) \
        : "r"((a)[0]), "r"((a)[1]), "r"((a)[2]), "r"((a)[3]), \
          "r"((b)[0]), "r"((b)[1]))

// dynamic smem plan (all fused kernels): 76288 bytes
//   iter1/node: As[128][132] floats | Wb[16][136] unsigned
//   gru:        SHs[64][132] | SGs[64][132] | Wb[16][136]
#define DYN_SMEM_BYTES 76288

// ---------------------------------------------------------------------------
// Index dtype normalize (JAX may ship int32 despite int64 in source).
// ---------------------------------------------------------------------------
__global__ void detect_idx_kernel(const unsigned int* __restrict__ w)
{
    g_idx_is64 = (w[1] == 0u && w[3] == 0u && w[5] == 0u && w[7] == 0u) ? 1 : 0;
}
__global__ void convert_idx_kernel(const void* __restrict__ src, int* __restrict__ dst, int n)
{
    int i = blockIdx.x * blockDim.x + threadIdx.x;
    if (i >= n) return;
    if (g_idx_is64) dst[i] = (int)((const long long*)src)[i];
    else            dst[i] = ((const int*)src)[i];
}

// ---------------------------------------------------------------------------
// GEMM helper: A resident in smem (tf32 bits stored as float, stride 132),
// C += A[.., k] @ W[k, 128] over K=128.  Wb is the W staging buffer.
// Warp tile = 32 x (NT*8); wr/wc give the warp's row/col origin.
// ---------------------------------------------------------------------------
template<int NT>
__device__ __forceinline__ void gemm_smemA(
    const float (*As)[132], const float* __restrict__ W,
    unsigned (*Wb)[136], float (&C)[2][NT][4],
    int wr, int wc, int gid, int tig, int tid)
{
    for (int k0 = 0; k0 < 128; k0 += 16) {
        {
            const int row = tid >> 4, cb = (tid & 15) * 8;
            const float* p = W + (size_t)(k0 + row) * H + cb;
            const float4 v0 = *(const float4*)p, v1 = *(const float4*)(p + 4);
            unsigned* d = &Wb[row][cb];
            d[0]=f2tf32(v0.x); d[1]=f2tf32(v0.y); d[2]=f2tf32(v0.z); d[3]=f2tf32(v0.w);
            d[4]=f2tf32(v1.x); d[5]=f2tf32(v1.y); d[6]=f2tf32(v1.z); d[7]=f2tf32(v1.w);
        }
        __syncthreads();
#pragma unroll
        for (int ks = 0; ks < 16; ks += 8) {
            unsigned a[2][4], b[NT][2];
#pragma unroll
            for (int mi = 0; mi < 2; ++mi) {
                a[mi][0] = __float_as_uint(As[wr + mi*16 + gid    ][k0 + ks + tig    ]);
                a[mi][1] = __float_as_uint(As[wr + mi*16 + gid + 8][k0 + ks + tig    ]);
                a[mi][2] = __float_as_uint(As[wr + mi*16 + gid    ][k0 + ks + tig + 4]);
                a[mi][3] = __float_as_uint(As[wr + mi*16 + gid + 8][k0 + ks + tig + 4]);
            }
#pragma unroll
            for (int ni = 0; ni < NT; ++ni) {
                b[ni][0] = Wb[ks + tig    ][wc + ni*8 + gid];
                b[ni][1] = Wb[ks + tig + 4][wc + ni*8 + gid];
            }
#pragma unroll
            for (int mi = 0; mi < 2; ++mi)
#pragma unroll
                for (int ni = 0; ni < NT; ++ni)
                    MMA_TF32(C[mi][ni], a[mi], b[ni]);
        }
        __syncthreads();
    }
}

// ---------------------------------------------------------------------------
// mm3: out[y] = X @ W[y] + bias[y]   (global-A, BM=128, proven)
// ---------------------------------------------------------------------------
__global__ void __launch_bounds__(256)
mm3_kernel(const float* __restrict__ X, int ldx, int M, int K,
           const float* __restrict__ W0, const float* __restrict__ W1, const float* __restrict__ W2,
           const float* __restrict__ b0, const float* __restrict__ b1, const float* __restrict__ b2,
           float* __restrict__ o0, float* __restrict__ o1, float* __restrict__ o2)
{
    __shared__ unsigned Xs[128][20];
    __shared__ unsigned Ws[16][136];

    const float* W   = (blockIdx.y == 0) ? W0 : (blockIdx.y == 1) ? W1 : W2;
    const float* bia = (blockIdx.y == 0) ? b0 : (blockIdx.y == 1) ? b1 : b2;
    float*       out = (blockIdx.y == 0) ? o0 : (blockIdx.y == 1) ? o1 : o2;

    const int tid = threadIdx.x, warp = tid >> 5, lane = tid & 31;
    const int gid = lane >> 2, tig = lane & 3;
    const int wr = (warp >> 1) * 32, wc = (warp & 1) * 64;
    const int brow = blockIdx.x * 128;

    float C[2][8][4];
#pragma unroll
    for (int i = 0; i < 2; ++i)
#pragma unroll
        for (int j = 0; j < 8; ++j)
#pragma unroll
            for (int k = 0; k < 4; ++k) C[i][j][k] = 0.f;

    for (int k0 = 0; k0 < K; k0 += 16) {
        {
            const int row = tid >> 1, cb = (tid & 1) * 8;
            const int gr  = brow + row;
            float4 v0 = make_float4(0.f,0.f,0.f,0.f), v1 = v0;
            if (gr < M) {
                const float* p = X + (size_t)gr * ldx + k0 + cb;
                v0 = *(const float4*)p; v1 = *(const float4*)(p + 4);
            }
            unsigned* d = &Xs[row][cb];
            d[0]=f2tf32(v0.x); d[1]=f2tf32(v0.y); d[2]=f2tf32(v0.z); d[3]=f2tf32(v0.w);
            d[4]=f2tf32(v1.x); d[5]=f2tf32(v1.y); d[6]=f2tf32(v1.z); d[7]=f2tf32(v1.w);
        }
        {
            const int row = tid >> 4, cb = (tid & 15) * 8;
            const float* p = W + (size_t)(k0 + row) * H + cb;
            const float4 v0 = *(const float4*)p, v1 = *(const float4*)(p + 4);
            unsigned* d = &Ws[row][cb];
            d[0]=f2tf32(v0.x); d[1]=f2tf32(v0.y); d[2]=f2tf32(v0.z); d[3]=f2tf32(v0.w);
            d[4]=f2tf32(v1.x); d[5]=f2tf32(v1.y); d[6]=f2tf32(v1.z); d[7]=f2tf32(v1.w);
        }
        __syncthreads();
#pragma unroll
        for (int ks = 0; ks < 16; ks += 8) {
            unsigned a[2][4], b[8][2];
#pragma unroll
            for (int mi = 0; mi < 2; ++mi) {
                a[mi][0] = Xs[wr + mi*16 + gid    ][ks + tig    ];
                a[mi][1] = Xs[wr + mi*16 + gid + 8][ks + tig    ];
                a[mi][2] = Xs[wr + mi*16 + gid    ][ks + tig + 4];
                a[mi][3] = Xs[wr + mi*16 + gid + 8][ks + tig + 4];
            }
#pragma unroll
            for (int ni = 0; ni < 8; ++ni) {
                b[ni][0] = Ws[ks + tig    ][wc + ni*8 + gid];
                b[ni][1] = Ws[ks + tig + 4][wc + ni*8 + gid];
            }
#pragma unroll
            for (int mi = 0; mi < 2; ++mi)
#pragma unroll
                for (int ni = 0; ni < 8; ++ni)
                    MMA_TF32(C[mi][ni], a[mi], b[ni]);
        }
        __syncthreads();
    }

#pragma unroll
    for (int mi = 0; mi < 2; ++mi)
#pragma unroll
        for (int ni = 0; ni < 8; ++ni) {
            const int col = wc + ni * 8 + 2 * tig;
            const float bx = bia ? bia[col] : 0.f;
            const float by = bia ? bia[col + 1] : 0.f;
            const int r0 = brow + wr + mi * 16 + gid;
            const int r1 = r0 + 8;
            if (r0 < M) *(float2*)&out[(size_t)r0 * H + col] =
                make_float2(C[mi][ni][0] + bx, C[mi][ni][1] + by);
            if (r1 < M) *(float2*)&out[(size_t)r1 * H + col] =
                make_float2(C[mi][ni][2] + bx, C[mi][ni][3] + by);
        }
}

// ---------------------------------------------------------------------------
// fused_iter1 (BM=128, dyn smem): h = sigmoid(Pz)*tanh(Ph) -> global + smem;
// then q = h @ Ur.   Warps 4x2, warp tile 32x64 (NT=8).
// ---------------------------------------------------------------------------
__global__ void __launch_bounds__(256)
fused_iter1_kernel(const float* __restrict__ Pz, const float* __restrict__ Ph,
                   const float* __restrict__ Ur,
                   float* __restrict__ h_out, float* __restrict__ q_out, int E)
{
    extern __shared__ float dyn[];
    float (*As)[132]    = (float(*)[132])dyn;
    unsigned (*Wb)[136] = (unsigned(*)[136])(dyn + 128 * 132);

    const int tid = threadIdx.x, lane = tid & 31, ty = tid >> 5;
    const int gid = lane >> 2, tig = lane & 3;
    const int wr = (ty >> 1) * 32, wc = (ty & 1) * 64;
    const int brow = blockIdx.x * 128;
    const int c4 = lane * 4;

    // phase 1: elementwise h
#pragma unroll
    for (int pass = 0; pass < 16; ++pass) {
        const int er = pass * 8 + ty;
        const int e  = brow + er;
        float4 v = make_float4(0.f,0.f,0.f,0.f);
        if (e < E) {
            const float4 pz = *(const float4*)&Pz[(size_t)e*H + c4];
            const float4 ph = *(const float4*)&Ph[(size_t)e*H + c4];
            v.x = sigmoidf_(pz.x) * tanhf(ph.x);
            v.y = sigmoidf_(pz.y) * tanhf(ph.y);
            v.z = sigmoidf_(pz.z) * tanhf(ph.z);
            v.w = sigmoidf_(pz.w) * tanhf(ph.w);
            if (e == 0) v = make_float4(0.f,0.f,0.f,0.f);
            *(float4*)&h_out[(size_t)e*H + c4] = v;
        }
        *(float4*)&As[er][c4] = make_float4(ftf32(v.x), ftf32(v.y), ftf32(v.z), ftf32(v.w));
    }

    // phase 2: q = h @ Ur
    float C[2][8][4];
#pragma unroll
    for (int i = 0; i < 2; ++i)
#pragma unroll
        for (int j = 0; j < 8; ++j)
#pragma unroll
            for (int k = 0; k < 4; ++k) C[i][j][k] = 0.f;
    gemm_smemA<8>(As, Ur, Wb, C, wr, wc, gid, tig, tid);

#pragma unroll
    for (int mi = 0; mi < 2; ++mi)
#pragma unroll
        for (int ni = 0; ni < 8; ++ni) {
            const int col = wc + ni * 8 + 2 * tig;
            const int r0 = brow + wr + mi * 16 + gid;
            const int r1 = r0 + 8;
            if (r0 < E) *(float2*)&q_out[(size_t)r0 * H + col] =
                make_float2(C[mi][ni][0], C[mi][ni][1]);
            if (r1 < E) *(float2*)&q_out[(size_t)r1 * H + col] =
                make_float2(C[mi][ni][2], C[mi][ni][3]);
        }
}

// ---------------------------------------------------------------------------
// fused_gru (BM=64, dyn smem): gather(sh,sg) -> smem; Cz=sh@Wz2, Ch=sg@Wh2;
// GRU epilogue -> h_out + smem(tf32); optional q_out = h_new @ Ur.
// Warps 2x4, warp tile 32x32 (NT=4).
// ---------------------------------------------------------------------------
__global__ void __launch_bounds__(256)
fused_gru_kernel(const float* __restrict__ h_in, const float* __restrict__ q_in,
                 const int* __restrict__ bg,
                 const float* __restrict__ Pr, const float* __restrict__ Pz,
                 const float* __restrict__ Ph,
                 const float* __restrict__ Wz2, const float* __restrict__ Wh2,
                 const float* __restrict__ Ur,
                 float* __restrict__ h_out, float* __restrict__ q_out,
                 int E, int do_q)
{
    extern __shared__ float dyn[];
    float (*SHs)[132]   = (float(*)[132])dyn;
    float (*SGs)[132]   = (float(*)[132])(dyn + 64 * 132);
    unsigned (*Wb)[136] = (unsigned(*)[136])(dyn + 2 * 64 * 132);

    const int tid = threadIdx.x, lane = tid & 31, ty = tid >> 5;
    const int gid = lane >> 2, tig = lane & 3;
    const int wr = (ty >> 2) * 32, wc = (ty & 3) * 32;
    const int brow = blockIdx.x * 64;
    const int c4 = lane * 4;

    // gather phase: 64 edges, 6 neighbors each
#pragma unroll
    for (int pass = 0; pass < 8; ++pass) {
        const int er = pass * 8 + ty;
        const int e  = brow + er;
        float4 sh = make_float4(0.f,0.f,0.f,0.f);
        float4 sg = make_float4(0.f,0.f,0.f,0.f);
        if (e < E) {
            const float4 pr = *(const float4*)&Pr[(size_t)e*H + c4];
#pragma unroll
            for (int j = 0; j < 6; ++j) {
                const int idx = __ldg(&bg[e * 6 + j]);
                const float4 hn = *(const float4*)&h_in[(size_t)idx*H + c4];
                const float4 qn = *(const float4*)&q_in[(size_t)idx*H + c4];
                sh.x += hn.x; sh.y += hn.y; sh.z += hn.z; sh.w += hn.w;
                sg.x += hn.x * sigmoidf_(pr.x + qn.x);
                sg.y += hn.y * sigmoidf_(pr.y + qn.y);
                sg.z += hn.z * sigmoidf_(pr.z + qn.z);
                sg.w += hn.w * sigmoidf_(pr.w + qn.w);
            }
        }
        *(float4*)&SHs[er][c4] = make_float4(ftf32(sh.x), ftf32(sh.y), ftf32(sh.z), ftf32(sh.w));
        *(float4*)&SGs[er][c4] = make_float4(ftf32(sg.x), ftf32(sg.y), ftf32(sg.z), ftf32(sg.w));
    }

    float Cz[2][4][4], Ch[2][4][4];
#pragma unroll
    for (int i = 0; i < 2; ++i)
#pragma unroll
        for (int j = 0; j < 4; ++j)
#pragma unroll
            for (int k = 0; k < 4; ++k) { Cz[i][j][k] = 0.f; Ch[i][j][k] = 0.f; }

    gemm_smemA<4>(SHs, Wz2, Wb, Cz, wr, wc, gid, tig, tid);
    gemm_smemA<4>(SGs, Wh2, Wb, Ch, wr, wc, gid, tig, tid);

    // GRU epilogue; write h_out, refill SHs with tf32(h_new) for q-GEMM
#pragma unroll
    for (int mi = 0; mi < 2; ++mi)
#pragma unroll
        for (int ni = 0; ni < 4; ++ni) {
            const int col = wc + ni * 8 + 2 * tig;
#pragma unroll
            for (int half = 0; half < 2; ++half) {
                const int lr  = wr + mi * 16 + gid + half * 8;
                const int row = brow + lr;
                if (row >= E) continue;
                const size_t base = (size_t)row * H + col;
                const float2 pz = *(const float2*)&Pz[base];
                const float2 ph = *(const float2*)&Ph[base];
                const float sh0 = SHs[lr][col], sh1 = SHs[lr][col + 1];
                const float z0 = sigmoidf_(Cz[mi][ni][half*2+0] + pz.x);
                const float z1 = sigmoidf_(Cz[mi][ni][half*2+1] + pz.y);
                const float p0 = tanhf(Ch[mi][ni][half*2+0] + ph.x);
                const float p1 = tanhf(Ch[mi][ni][half*2+1] + ph.y);
                float o0 = (1.f - z0) * sh0 + z0 * p0;
                float o1 = (1.f - z1) * sh1 + z1 * p1;
                if (row == 0) { o0 = 0.f; o1 = 0.f; }
                *(float2*)&h_out[base] = make_float2(o0, o1);
                SHs[lr][col]     = ftf32(o0);
                SHs[lr][col + 1] = ftf32(o1);
            }
        }
    if (!do_q) return;
    __syncthreads();

    // q = h_new @ Ur
    float Cq[2][4][4];
#pragma unroll
    for (int i = 0; i < 2; ++i)
#pragma unroll
        for (int j = 0; j < 4; ++j)
#pragma unroll
            for (int k = 0; k < 4; ++k) Cq[i][j][k] = 0.f;
    gemm_smemA<4>(SHs, Ur, Wb, Cq, wr, wc, gid, tig, tid);

#pragma unroll
    for (int mi = 0; mi < 2; ++mi)
#pragma unroll
        for (int ni = 0; ni < 4; ++ni) {
            const int col = wc + ni * 8 + 2 * tig;
            const int r0 = brow + wr + mi * 16 + gid;
            const int r1 = r0 + 8;
            if (r0 < E) *(float2*)&q_out[(size_t)r0 * H + col] =
                make_float2(Cq[mi][ni][0], Cq[mi][ni][1]);
            if (r1 < E) *(float2*)&q_out[(size_t)r1 * H + col] =
                make_float2(Cq[mi][ni][2], Cq[mi][ni][3]);
        }
}

// ---------------------------------------------------------------------------
// fused_node (BM=128, dyn smem): C = fnode @ Wo[0:256] + gather(nei) @ Wo[256:384]
// epilogue relu(+bo), row0 mask.  Warps 4x2, warp tile 32x64 (NT=8).
// ---------------------------------------------------------------------------
__global__ void __launch_bounds__(256)
fused_node_kernel(const float* __restrict__ fnode, const float* __restrict__ Wo,
                  const float* __restrict__ h, const int* __restrict__ ag,
                  const float* __restrict__ bo, float* __restrict__ out, int N)
{
    extern __shared__ float dyn[];
    float (*As)[132]    = (float(*)[132])dyn;
    unsigned (*Wb)[136] = (unsigned(*)[136])(dyn + 128 * 132);

    const int tid = threadIdx.x, lane = tid & 31, ty = tid >> 5;
    const int gid = lane >> 2, tig = lane & 3;
    const int wr = (ty >> 1) * 32, wc = (ty & 1) * 64;
    const int brow = blockIdx.x * 128;
    const int c4 = lane * 4;

    float C[2][8][4];
#pragma unroll
    for (int i = 0; i < 2; ++i)
#pragma unroll
        for (int j = 0; j < 8; ++j)
#pragma unroll
            for (int k = 0; k < 4; ++k) C[i][j][k] = 0.f;

    // phase A: fnode @ Wo[0:256], chunked staging into As cols [0,16)
    for (int k0 = 0; k0 < 256; k0 += 16) {
        {
            const int row = tid >> 1, cb = (tid & 1) * 8;
            const int gr  = brow + row;
            float4 v0 = make_float4(0.f,0.f,0.f,0.f), v1 = v0;
            if (gr < N) {
                const float* p = &fnode[(size_t)gr * 256 + k0 + cb];
                v0 = *(const float4*)p; v1 = *(const float4*)(p + 4);
            }
            float* d = &As[row][cb];
            d[0]=ftf32(v0.x); d[1]=ftf32(v0.y); d[2]=ftf32(v0.z); d[3]=ftf32(v0.w);
            d[4]=ftf32(v1.x); d[5]=ftf32(v1.y); d[6]=ftf32(v1.z); d[7]=ftf32(v1.w);
        }
        {
            const int row = tid >> 4, cb = (tid & 15) * 8;
            const float* p = Wo + (size_t)(k0 + row) * H + cb;
            const float4 v0 = *(const float4*)p, v1 = *(const float4*)(p + 4);
            unsigned* d = &Wb[row][cb];
            d[0]=f2tf32(v0.x); d[1]=f2tf32(v0.y); d[2]=f2tf32(v0.z); d[3]=f2tf32(v0.w);
            d[4]=f2tf32(v1.x); d[5]=f2tf32(v1.y); d[6]=f2tf32(v1.z); d[7]=f2tf32(v1.w);
        }
        __syncthreads();
#pragma unroll
        for (int ks = 0; ks < 16; ks += 8) {
            unsigned a[2][4], b[8][2];
#pragma unroll
            for (int mi = 0; mi < 2; ++mi) {
                a[mi][0] = __float_as_uint(As[wr + mi*16 + gid    ][ks + tig    ]);
                a[mi][1] = __float_as_uint(As[wr + mi*16 + gid + 8][ks + tig    ]);
                a[mi][2] = __float_as_uint(As[wr + mi*16 + gid    ][ks + tig + 4]);
                a[mi][3] = __float_as_uint(As[wr + mi*16 + gid + 8][ks + tig + 4]);
            }
#pragma unroll
            for (int ni = 0; ni < 8; ++ni) {
                b[ni][0] = Wb[ks + tig    ][wc + ni*8 + gid];
                b[ni][1] = Wb[ks + tig + 4][wc + ni*8 + gid];
            }
#pragma unroll
            for (int mi = 0; mi < 2; ++mi)
#pragma unroll
                for (int ni = 0; ni < 8; ++ni)
                    MMA_TF32(C[mi][ni], a[mi], b[ni]);
        }
        __syncthreads();
    }

    // phase B: gather nei into As (full width, tf32)
#pragma unroll
    for (int pass = 0; pass < 16; ++pass) {
        const int nr = pass * 8 + ty;
        const int n  = brow + nr;
        float4 s = make_float4(0.f,0.f,0.f,0.f);
        if (n < N) {
#pragma unroll
            for (int j = 0; j < 6; ++j) {
                const int idx = __ldg(&ag[n * 6 + j]);
                const float4 hn = *(const float4*)&h[(size_t)idx*H + c4];
                s.x += hn.x; s.y += hn.y; s.z += hn.z; s.w += hn.w;
            }
        }
        *(float4*)&As[nr][c4] = make_float4(ftf32(s.x), ftf32(s.y), ftf32(s.z), ftf32(s.w));
    }

    gemm_smemA<8>(As, Wo + 256 * H, Wb, C, wr, wc, gid, tig, tid);

#pragma unroll
    for (int mi = 0; mi < 2; ++mi)
#pragma unroll
        for (int ni = 0; ni < 8; ++ni) {
            const int col = wc + ni * 8 + 2 * tig;
            const float bx = bo[col], by = bo[col + 1];
#pragma unroll
            for (int half = 0; half < 2; ++half) {
                const int row = brow + wr + mi * 16 + gid + half * 8;
                if (row >= N) continue;
                float o0 = fmaxf(C[mi][ni][half*2+0] + bx, 0.f);
                float o1 = fmaxf(C[mi][ni][half*2+1] + by, 0.f);
                if (row == 0) { o0 = 0.f; o1 = 0.f; }
                *(float2*)&out[(size_t)row * H + col] = make_float2(o0, o1);
            }
        }
}

// ---------------------------------------------------------------------------
extern "C" void kernel_launch(void* const* d_in, const int* in_sizes, int n_in,
                              void* d_out, int out_size)
{
    const float* fnode  = (const float*) d_in[0];
    const float* fmess  = (const float*) d_in[1];
    const void*  agraph = d_in[2];
    const void*  bgraph = d_in[3];
    const float* Wz     = (const float*) d_in[4];
    const float* bz     = (const float*) d_in[5];
    const float* Wr     = (const float*) d_in[6];
    const float* Ur     = (const float*) d_in[7];
    const float* bur    = (const float*) d_in[8];
    const float* Wh     = (const float*) d_in[9];
    const float* bh     = (const float*) d_in[10];
    const float* Wo     = (const float*) d_in[11];
    const float* bo     = (const float*) d_in[12];

    const int N = in_sizes[2] / 6;
    const int E = in_sizes[3] / 6;

    float *Pz, *Pr, *Ph, *q1, *q2, *hA, *hB;
    int *bg32, *ag32;
    cudaGetSymbolAddress((void**)&Pz,   g_Pz);
    cudaGetSymbolAddress((void**)&Pr,   g_Pr);
    cudaGetSymbolAddress((void**)&Ph,   g_Ph);
    cudaGetSymbolAddress((void**)&q1,   g_q1);
    cudaGetSymbolAddress((void**)&q2,   g_q2);
    cudaGetSymbolAddress((void**)&hA,   g_hA);
    cudaGetSymbolAddress((void**)&hB,   g_hB);
    cudaGetSymbolAddress((void**)&bg32, g_bg32);
    cudaGetSymbolAddress((void**)&ag32, g_ag32);

    float* out_node = (float*)d_out;
    const long long need = (long long)(N + E) * H;
    const bool out_has_h = ((long long)out_size >= need);
    float* h_final = out_has_h ? ((float*)d_out + (size_t)N * H) : hA;

    // allow >48KB dynamic smem (idempotent; safe under graph capture)
    cudaFuncSetAttribute(fused_iter1_kernel,
                         cudaFuncAttributeMaxDynamicSharedMemorySize, DYN_SMEM_BYTES);
    cudaFuncSetAttribute(fused_gru_kernel,
                         cudaFuncAttributeMaxDynamicSharedMemorySize, DYN_SMEM_BYTES);
    cudaFuncSetAttribute(fused_node_kernel,
                         cudaFuncAttributeMaxDynamicSharedMemorySize, DYN_SMEM_BYTES);

    detect_idx_kernel<<<1, 1>>>((const unsigned int*)bgraph);
    convert_idx_kernel<<<(E * 6 + 255) / 256, 256>>>(bgraph, bg32, E * 6);
    convert_idx_kernel<<<(N * 6 + 255) / 256, 256>>>(agraph, ag32, N * 6);

    const int gE128 = (E + 127) / 128;
    const int gE64  = (E + 63) / 64;
    const int gN128 = (N + 127) / 128;

    // loop-invariant precompute (tensor cores, one launch):
    mm3_kernel<<<dim3(gE128, 3), 256>>>(fmess, 384, E, 384,
                                        Wz, Wr, Wh, bz, bur, bh, Pz, Pr, Ph);

    // iteration 1 (h=0): elementwise h + fused q = h@Ur
    fused_iter1_kernel<<<gE128, 256, DYN_SMEM_BYTES>>>(Pz, Ph, Ur, hA, q1, E);

    // iteration 2: gather + dual GEMM + GRU + fused q
    fused_gru_kernel<<<gE64, 256, DYN_SMEM_BYTES>>>(hA, q1, bg32, Pr, Pz, Ph,
                                    Wz + 384 * H, Wh + 384 * H, Ur, hB, q2, E, 1);

    // iteration 3: final h (no q needed)
    fused_gru_kernel<<<gE64, 256, DYN_SMEM_BYTES>>>(hB, q2, bg32, Pr, Pz, Ph,
                                    Wz + 384 * H, Wh + 384 * H, Ur, h_final, q1, E, 0);

    // output head: fused gather + dual-segment GEMM
    fused_node_kernel<<<gN128, 256, DYN_SMEM_BYTES>>>(fnode, Wo, h_final, ag32, bo, out_node, N);
}

// round 9
// speedup vs baseline: 1.3226x; 1.3226x over previous
#include <cuda_runtime.h>
#include <math.h>

#define H 128
#define E_MAX 80000
#define N_MAX 40000

// ---------------- scratch (device globals; no allocation allowed) ----------
__device__ __align__(16) float g_Pz [E_MAX * H];
__device__ __align__(16) float g_Pr [E_MAX * H];
__device__ __align__(16) float g_Ph [E_MAX * H];
__device__ __align__(16) float g_q1 [E_MAX * H];
__device__ __align__(16) float g_q2 [E_MAX * H];
__device__ __align__(16) float g_hA [E_MAX * H];
__device__ __align__(16) float g_hB [E_MAX * H];
__device__ int g_bg32[E_MAX * 6];
__device__ int g_ag32[N_MAX * 6];
__device__ int g_idx_is64;

__device__ __forceinline__ float sigmoidf_(float x) { return 1.0f / (1.0f + expf(-x)); }
__device__ __forceinline__ unsigned f2tf32(float f) {
    unsigned u; asm("cvt.rna.tf32.f32 %0, %1;" : "=r"(u) : "f"(f)); return u;
}
__device__ __forceinline__ float ftf32(float f) {
    unsigned u; asm("cvt.rna.tf32.f32 %0, %1;" : "=r"(u) : "f"(f));
    return __uint_as_float(u);
}

#define MMA_TF32(C, a, b) \
    asm volatile("mma.sync.aligned.m16n8k8.row.col.f32.tf32.tf32.f32 " \
        "{%0,%1,%2,%3},{%4,%5,%6,%7},{%8,%9},{%0,%1,%2,%3};" \
        : "+f"((C)[0]), "+f"((C)[1]), "+f"((C)[2]), "+f"((C)[3]) \
        : "r"((a)[0]), "r"((a)[1]), "r"((a)[2]), "r"((a)[3]), \
          "r"((b)[0]), "r"((b)[1]))

// ---------------------------------------------------------------------------
// Index dtype normalize (JAX may ship int32 despite int64 in source).
// ---------------------------------------------------------------------------
__global__ void detect_idx_kernel(const unsigned int* __restrict__ w)
{
    g_idx_is64 = (w[1] == 0u && w[3] == 0u && w[5] == 0u && w[7] == 0u) ? 1 : 0;
}
__global__ void convert_idx_kernel(const void* __restrict__ src, int* __restrict__ dst, int n)
{
    int i = blockIdx.x * blockDim.x + threadIdx.x;
    if (i >= n) return;
    if (g_idx_is64) dst[i] = (int)((const long long*)src)[i];
    else            dst[i] = ((const int*)src)[i];
}

// ---------------------------------------------------------------------------
// GEMM helper: A resident in smem (tf32 bits stored as float, stride 132),
// C += A[.., k] @ W[k, 128] over K=128.  Wb is the W staging buffer.
// Warp tile = 32 x (NT*8); wr/wc give the warp's row/col origin.
// ---------------------------------------------------------------------------
template<int NT>
__device__ __forceinline__ void gemm_smemA(
    const float (*As)[132], const float* __restrict__ W,
    unsigned (*Wb)[136], float (&C)[2][NT][4],
    int wr, int wc, int gid, int tig, int tid)
{
    for (int k0 = 0; k0 < 128; k0 += 16) {
        {
            const int row = tid >> 4, cb = (tid & 15) * 8;
            const float* p = W + (size_t)(k0 + row) * H + cb;
            const float4 v0 = *(const float4*)p, v1 = *(const float4*)(p + 4);
            unsigned* d = &Wb[row][cb];
            d[0]=f2tf32(v0.x); d[1]=f2tf32(v0.y); d[2]=f2tf32(v0.z); d[3]=f2tf32(v0.w);
            d[4]=f2tf32(v1.x); d[5]=f2tf32(v1.y); d[6]=f2tf32(v1.z); d[7]=f2tf32(v1.w);
        }
        __syncthreads();
#pragma unroll
        for (int ks = 0; ks < 16; ks += 8) {
            unsigned a[2][4], b[NT][2];
#pragma unroll
            for (int mi = 0; mi < 2; ++mi) {
                a[mi][0] = __float_as_uint(As[wr + mi*16 + gid    ][k0 + ks + tig    ]);
                a[mi][1] = __float_as_uint(As[wr + mi*16 + gid + 8][k0 + ks + tig    ]);
                a[mi][2] = __float_as_uint(As[wr + mi*16 + gid    ][k0 + ks + tig + 4]);
                a[mi][3] = __float_as_uint(As[wr + mi*16 + gid + 8][k0 + ks + tig + 4]);
            }
#pragma unroll
            for (int ni = 0; ni < NT; ++ni) {
                b[ni][0] = Wb[ks + tig    ][wc + ni*8 + gid];
                b[ni][1] = Wb[ks + tig + 4][wc + ni*8 + gid];
            }
#pragma unroll
            for (int mi = 0; mi < 2; ++mi)
#pragma unroll
                for (int ni = 0; ni < NT; ++ni)
                    MMA_TF32(C[mi][ni], a[mi], b[ni]);
        }
        __syncthreads();
    }
}

// ---------------------------------------------------------------------------
// mm3: out[y] = X @ W[y] + bias[y]   (global-A, BM=128)
// Double-buffered smem pipeline: LDG(k+1) -> compute(k) -> cvt+STS(k+1).
// ---------------------------------------------------------------------------
__global__ void __launch_bounds__(256)
mm3_kernel(const float* __restrict__ X, int ldx, int M, int K,
           const float* __restrict__ W0, const float* __restrict__ W1, const float* __restrict__ W2,
           const float* __restrict__ b0, const float* __restrict__ b1, const float* __restrict__ b2,
           float* __restrict__ o0, float* __restrict__ o1, float* __restrict__ o2)
{
    __shared__ unsigned Xs[2][128][20];
    __shared__ unsigned Ws[2][16][136];

    const float* W   = (blockIdx.y == 0) ? W0 : (blockIdx.y == 1) ? W1 : W2;
    const float* bia = (blockIdx.y == 0) ? b0 : (blockIdx.y == 1) ? b1 : b2;
    float*       out = (blockIdx.y == 0) ? o0 : (blockIdx.y == 1) ? o1 : o2;

    const int tid = threadIdx.x, warp = tid >> 5, lane = tid & 31;
    const int gid = lane >> 2, tig = lane & 3;
    const int wr = (warp >> 1) * 32, wc = (warp & 1) * 64;
    const int brow = blockIdx.x * 128;

    // staging roles
    const int xrow = tid >> 1, xcb = (tid & 1) * 8;
    const int wrow = tid >> 4, wcb = (tid & 15) * 8;
    const int xgr  = brow + xrow;

    float C[2][8][4];
#pragma unroll
    for (int i = 0; i < 2; ++i)
#pragma unroll
        for (int j = 0; j < 8; ++j)
#pragma unroll
            for (int k = 0; k < 4; ++k) C[i][j][k] = 0.f;

    float4 xv0, xv1, wv0, wv1;

    // ---- prefetch tile 0: LDG ----
    {
        xv0 = make_float4(0.f,0.f,0.f,0.f); xv1 = xv0;
        if (xgr < M) {
            const float* p = X + (size_t)xgr * ldx + xcb;
            xv0 = *(const float4*)p; xv1 = *(const float4*)(p + 4);
        }
        const float* wp = W + (size_t)wrow * H + wcb;
        wv0 = *(const float4*)wp; wv1 = *(const float4*)(wp + 4);
    }
    // ---- cvt + STS tile 0 ----
    {
        uint4 a = make_uint4(f2tf32(xv0.x), f2tf32(xv0.y), f2tf32(xv0.z), f2tf32(xv0.w));
        uint4 b = make_uint4(f2tf32(xv1.x), f2tf32(xv1.y), f2tf32(xv1.z), f2tf32(xv1.w));
        *(uint4*)&Xs[0][xrow][xcb]     = a;
        *(uint4*)&Xs[0][xrow][xcb + 4] = b;
        uint4 c = make_uint4(f2tf32(wv0.x), f2tf32(wv0.y), f2tf32(wv0.z), f2tf32(wv0.w));
        uint4 d = make_uint4(f2tf32(wv1.x), f2tf32(wv1.y), f2tf32(wv1.z), f2tf32(wv1.w));
        *(uint4*)&Ws[0][wrow][wcb]     = c;
        *(uint4*)&Ws[0][wrow][wcb + 4] = d;
    }
    __syncthreads();

    const int nk = K >> 4;
    for (int it = 0; it < nk; ++it) {
        const int buf = it & 1;
        // ---- LDG tile it+1 (latency hidden under compute) ----
        if (it + 1 < nk) {
            const int k0 = (it + 1) << 4;
            xv0 = make_float4(0.f,0.f,0.f,0.f); xv1 = xv0;
            if (xgr < M) {
                const float* p = X + (size_t)xgr * ldx + k0 + xcb;
                xv0 = *(const float4*)p; xv1 = *(const float4*)(p + 4);
            }
            const float* wp = W + (size_t)(k0 + wrow) * H + wcb;
            wv0 = *(const float4*)wp; wv1 = *(const float4*)(wp + 4);
        }
        // ---- compute on buf ----
#pragma unroll
        for (int ks = 0; ks < 16; ks += 8) {
            unsigned a[2][4], b[8][2];
#pragma unroll
            for (int mi = 0; mi < 2; ++mi) {
                a[mi][0] = Xs[buf][wr + mi*16 + gid    ][ks + tig    ];
                a[mi][1] = Xs[buf][wr + mi*16 + gid + 8][ks + tig    ];
                a[mi][2] = Xs[buf][wr + mi*16 + gid    ][ks + tig + 4];
                a[mi][3] = Xs[buf][wr + mi*16 + gid + 8][ks + tig + 4];
            }
#pragma unroll
            for (int ni = 0; ni < 8; ++ni) {
                b[ni][0] = Ws[buf][ks + tig    ][wc + ni*8 + gid];
                b[ni][1] = Ws[buf][ks + tig + 4][wc + ni*8 + gid];
            }
#pragma unroll
            for (int mi = 0; mi < 2; ++mi)
#pragma unroll
                for (int ni = 0; ni < 8; ++ni)
                    MMA_TF32(C[mi][ni], a[mi], b[ni]);
        }
        // ---- cvt + STS tile it+1 into the other buffer ----
        if (it + 1 < nk) {
            const int nb = buf ^ 1;
            uint4 a = make_uint4(f2tf32(xv0.x), f2tf32(xv0.y), f2tf32(xv0.z), f2tf32(xv0.w));
            uint4 b = make_uint4(f2tf32(xv1.x), f2tf32(xv1.y), f2tf32(xv1.z), f2tf32(xv1.w));
            *(uint4*)&Xs[nb][xrow][xcb]     = a;
            *(uint4*)&Xs[nb][xrow][xcb + 4] = b;
            uint4 c = make_uint4(f2tf32(wv0.x), f2tf32(wv0.y), f2tf32(wv0.z), f2tf32(wv0.w));
            uint4 d = make_uint4(f2tf32(wv1.x), f2tf32(wv1.y), f2tf32(wv1.z), f2tf32(wv1.w));
            *(uint4*)&Ws[nb][wrow][wcb]     = c;
            *(uint4*)&Ws[nb][wrow][wcb + 4] = d;
        }
        __syncthreads();
    }

#pragma unroll
    for (int mi = 0; mi < 2; ++mi)
#pragma unroll
        for (int ni = 0; ni < 8; ++ni) {
            const int col = wc + ni * 8 + 2 * tig;
            const float bx = bia ? bia[col] : 0.f;
            const float by = bia ? bia[col + 1] : 0.f;
            const int r0 = brow + wr + mi * 16 + gid;
            const int r1 = r0 + 8;
            if (r0 < M) *(float2*)&out[(size_t)r0 * H + col] =
                make_float2(C[mi][ni][0] + bx, C[mi][ni][1] + by);
            if (r1 < M) *(float2*)&out[(size_t)r1 * H + col] =
                make_float2(C[mi][ni][2] + bx, C[mi][ni][3] + by);
        }
}

// ---------------------------------------------------------------------------
// fused_iter1 (R7 config): h = sigmoid(Pz)*tanh(Ph) -> global + smem(tf32);
// then q = h @ Ur.   BM=64, warps 2x4 (warp tile 32x32).
// ---------------------------------------------------------------------------
__global__ void __launch_bounds__(256)
fused_iter1_kernel(const float* __restrict__ Pz, const float* __restrict__ Ph,
                   const float* __restrict__ Ur,
                   float* __restrict__ h_out, float* __restrict__ q_out, int E)
{
    __shared__ float As[64][132];
    __shared__ unsigned Wb[16][136];

    const int tid = threadIdx.x, lane = tid & 31, ty = tid >> 5;
    const int gid = lane >> 2, tig = lane & 3;
    const int wr = (ty >> 2) * 32, wc = (ty & 3) * 32;
    const int brow = blockIdx.x * 64;
    const int c4 = lane * 4;

#pragma unroll
    for (int pass = 0; pass < 8; ++pass) {
        const int er = pass * 8 + ty;
        const int e  = brow + er;
        float4 v = make_float4(0.f,0.f,0.f,0.f);
        if (e < E) {
            const float4 pz = *(const float4*)&Pz[(size_t)e*H + c4];
            const float4 ph = *(const float4*)&Ph[(size_t)e*H + c4];
            v.x = sigmoidf_(pz.x) * tanhf(ph.x);
            v.y = sigmoidf_(pz.y) * tanhf(ph.y);
            v.z = sigmoidf_(pz.z) * tanhf(ph.z);
            v.w = sigmoidf_(pz.w) * tanhf(ph.w);
            if (e == 0) v = make_float4(0.f,0.f,0.f,0.f);
            *(float4*)&h_out[(size_t)e*H + c4] = v;
        }
        *(float4*)&As[er][c4] = make_float4(ftf32(v.x), ftf32(v.y), ftf32(v.z), ftf32(v.w));
    }
    __syncthreads();

    float C[2][4][4];
#pragma unroll
    for (int i = 0; i < 2; ++i)
#pragma unroll
        for (int j = 0; j < 4; ++j)
#pragma unroll
            for (int k = 0; k < 4; ++k) C[i][j][k] = 0.f;
    gemm_smemA<4>(As, Ur, Wb, C, wr, wc, gid, tig, tid);

#pragma unroll
    for (int mi = 0; mi < 2; ++mi)
#pragma unroll
        for (int ni = 0; ni < 4; ++ni) {
            const int col = wc + ni * 8 + 2 * tig;
            const int r0 = brow + wr + mi * 16 + gid;
            const int r1 = r0 + 8;
            if (r0 < E) *(float2*)&q_out[(size_t)r0 * H + col] =
                make_float2(C[mi][ni][0], C[mi][ni][1]);
            if (r1 < E) *(float2*)&q_out[(size_t)r1 * H + col] =
                make_float2(C[mi][ni][2], C[mi][ni][3]);
        }
}

// ---------------------------------------------------------------------------
// fused_gru (R7 config): BM=32, warps 1x8 (warp tile 32x16).
// gather(sh,sg) -> smem; Cz=sh@Wz2, Ch=sg@Wh2; GRU epilogue -> h_out +
// smem(tf32); optional q_out = h_new @ Ur.
// ---------------------------------------------------------------------------
__global__ void __launch_bounds__(256)
fused_gru_kernel(const float* __restrict__ h_in, const float* __restrict__ q_in,
                 const int* __restrict__ bg,
                 const float* __restrict__ Pr, const float* __restrict__ Pz,
                 const float* __restrict__ Ph,
                 const float* __restrict__ Wz2, const float* __restrict__ Wh2,
                 const float* __restrict__ Ur,
                 float* __restrict__ h_out, float* __restrict__ q_out,
                 int E, int do_q)
{
    __shared__ float SHs[32][132];
    __shared__ float SGs[32][132];
    __shared__ unsigned Wb[16][136];

    const int tid = threadIdx.x, lane = tid & 31, ty = tid >> 5;
    const int gid = lane >> 2, tig = lane & 3;
    const int wc = ty * 16;
    const int brow = blockIdx.x * 32;
    const int c4 = lane * 4;

#pragma unroll
    for (int pass = 0; pass < 4; ++pass) {
        const int er = pass * 8 + ty;
        const int e  = brow + er;
        float4 sh = make_float4(0.f,0.f,0.f,0.f);
        float4 sg = make_float4(0.f,0.f,0.f,0.f);
        if (e < E) {
            const float4 pr = *(const float4*)&Pr[(size_t)e*H + c4];
#pragma unroll
            for (int j = 0; j < 6; ++j) {
                const int idx = __ldg(&bg[e * 6 + j]);
                const float4 hn = *(const float4*)&h_in[(size_t)idx*H + c4];
                const float4 qn = *(const float4*)&q_in[(size_t)idx*H + c4];
                sh.x += hn.x; sh.y += hn.y; sh.z += hn.z; sh.w += hn.w;
                sg.x += hn.x * sigmoidf_(pr.x + qn.x);
                sg.y += hn.y * sigmoidf_(pr.y + qn.y);
                sg.z += hn.z * sigmoidf_(pr.z + qn.z);
                sg.w += hn.w * sigmoidf_(pr.w + qn.w);
            }
        }
        *(float4*)&SHs[er][c4] = make_float4(ftf32(sh.x), ftf32(sh.y), ftf32(sh.z), ftf32(sh.w));
        *(float4*)&SGs[er][c4] = make_float4(ftf32(sg.x), ftf32(sg.y), ftf32(sg.z), ftf32(sg.w));
    }

    float Cz[2][2][4], Ch[2][2][4];
#pragma unroll
    for (int i = 0; i < 2; ++i)
#pragma unroll
        for (int j = 0; j < 2; ++j)
#pragma unroll
            for (int k = 0; k < 4; ++k) { Cz[i][j][k] = 0.f; Ch[i][j][k] = 0.f; }

    gemm_smemA<2>(SHs, Wz2, Wb, Cz, 0, wc, gid, tig, tid);
    gemm_smemA<2>(SGs, Wh2, Wb, Ch, 0, wc, gid, tig, tid);

#pragma unroll
    for (int mi = 0; mi < 2; ++mi)
#pragma unroll
        for (int ni = 0; ni < 2; ++ni) {
            const int col = wc + ni * 8 + 2 * tig;
#pragma unroll
            for (int half = 0; half < 2; ++half) {
                const int lr  = mi * 16 + gid + half * 8;
                const int row = brow + lr;
                if (row >= E) continue;
                const size_t base = (size_t)row * H + col;
                const float2 pz = *(const float2*)&Pz[base];
                const float2 ph = *(const float2*)&Ph[base];
                const float sh0 = SHs[lr][col], sh1 = SHs[lr][col + 1];
                const float z0 = sigmoidf_(Cz[mi][ni][half*2+0] + pz.x);
                const float z1 = sigmoidf_(Cz[mi][ni][half*2+1] + pz.y);
                const float p0 = tanhf(Ch[mi][ni][half*2+0] + ph.x);
                const float p1 = tanhf(Ch[mi][ni][half*2+1] + ph.y);
                float o0 = (1.f - z0) * sh0 + z0 * p0;
                float o1 = (1.f - z1) * sh1 + z1 * p1;
                if (row == 0) { o0 = 0.f; o1 = 0.f; }
                *(float2*)&h_out[base] = make_float2(o0, o1);
                SHs[lr][col]     = ftf32(o0);
                SHs[lr][col + 1] = ftf32(o1);
            }
        }
    if (!do_q) return;
    __syncthreads();

    float Cq[2][2][4];
#pragma unroll
    for (int i = 0; i < 2; ++i)
#pragma unroll
        for (int j = 0; j < 2; ++j)
#pragma unroll
            for (int k = 0; k < 4; ++k) Cq[i][j][k] = 0.f;
    gemm_smemA<2>(SHs, Ur, Wb, Cq, 0, wc, gid, tig, tid);

#pragma unroll
    for (int mi = 0; mi < 2; ++mi)
#pragma unroll
        for (int ni = 0; ni < 2; ++ni) {
            const int col = wc + ni * 8 + 2 * tig;
            const int r0 = brow + mi * 16 + gid;
            const int r1 = r0 + 8;
            if (r0 < E) *(float2*)&q_out[(size_t)r0 * H + col] =
                make_float2(Cq[mi][ni][0], Cq[mi][ni][1]);
            if (r1 < E) *(float2*)&q_out[(size_t)r1 * H + col] =
                make_float2(Cq[mi][ni][2], Cq[mi][ni][3]);
        }
}

// ---------------------------------------------------------------------------
// fused_node (R7 config): BM=64, warps 2x4.
// C = fnode @ Wo[0:256] + gather(nei) @ Wo[256:384]; relu(+bo), row0 mask.
// ---------------------------------------------------------------------------
__global__ void __launch_bounds__(256)
fused_node_kernel(const float* __restrict__ fnode, const float* __restrict__ Wo,
                  const float* __restrict__ h, const int* __restrict__ ag,
                  const float* __restrict__ bo, float* __restrict__ out, int N)
{
    __shared__ float As[64][132];
    __shared__ unsigned Wb[16][136];

    const int tid = threadIdx.x, lane = tid & 31, ty = tid >> 5;
    const int gid = lane >> 2, tig = lane & 3;
    const int wr = (ty >> 2) * 32, wc = (ty & 3) * 32;
    const int brow = blockIdx.x * 64;
    const int c4 = lane * 4;

    float C[2][4][4];
#pragma unroll
    for (int i = 0; i < 2; ++i)
#pragma unroll
        for (int j = 0; j < 4; ++j)
#pragma unroll
            for (int k = 0; k < 4; ++k) C[i][j][k] = 0.f;

    for (int k0 = 0; k0 < 256; k0 += 16) {
        {
            const int row = tid >> 2, cb = (tid & 3) * 4;
            const int gr  = brow + row;
            float4 v = make_float4(0.f,0.f,0.f,0.f);
            if (gr < N) v = *(const float4*)&fnode[(size_t)gr * 256 + k0 + cb];
            *(float4*)&As[row][cb] = make_float4(ftf32(v.x), ftf32(v.y), ftf32(v.z), ftf32(v.w));
        }
        {
            const int row = tid >> 4, cb = (tid & 15) * 8;
            const float* p = Wo + (size_t)(k0 + row) * H + cb;
            const float4 v0 = *(const float4*)p, v1 = *(const float4*)(p + 4);
            unsigned* d = &Wb[row][cb];
            d[0]=f2tf32(v0.x); d[1]=f2tf32(v0.y); d[2]=f2tf32(v0.z); d[3]=f2tf32(v0.w);
            d[4]=f2tf32(v1.x); d[5]=f2tf32(v1.y); d[6]=f2tf32(v1.z); d[7]=f2tf32(v1.w);
        }
        __syncthreads();
#pragma unroll
        for (int ks = 0; ks < 16; ks += 8) {
            unsigned a[2][4], b[4][2];
#pragma unroll
            for (int mi = 0; mi < 2; ++mi) {
                a[mi][0] = __float_as_uint(As[wr + mi*16 + gid    ][ks + tig    ]);
                a[mi][1] = __float_as_uint(As[wr + mi*16 + gid + 8][ks + tig    ]);
                a[mi][2] = __float_as_uint(As[wr + mi*16 + gid    ][ks + tig + 4]);
                a[mi][3] = __float_as_uint(As[wr + mi*16 + gid + 8][ks + tig + 4]);
            }
#pragma unroll
            for (int ni = 0; ni < 4; ++ni) {
                b[ni][0] = Wb[ks + tig    ][wc + ni*8 + gid];
                b[ni][1] = Wb[ks + tig + 4][wc + ni*8 + gid];
            }
#pragma unroll
            for (int mi = 0; mi < 2; ++mi)
#pragma unroll
                for (int ni = 0; ni < 4; ++ni)
                    MMA_TF32(C[mi][ni], a[mi], b[ni]);
        }
        __syncthreads();
    }

#pragma unroll
    for (int pass = 0; pass < 8; ++pass) {
        const int nr = pass * 8 + ty;
        const int n  = brow + nr;
        float4 s = make_float4(0.f,0.f,0.f,0.f);
        if (n < N) {
#pragma unroll
            for (int j = 0; j < 6; ++j) {
                const int idx = __ldg(&ag[n * 6 + j]);
                const float4 hn = *(const float4*)&h[(size_t)idx*H + c4];
                s.x += hn.x; s.y += hn.y; s.z += hn.z; s.w += hn.w;
            }
        }
        *(float4*)&As[nr][c4] = make_float4(ftf32(s.x), ftf32(s.y), ftf32(s.z), ftf32(s.w));
    }
    __syncthreads();

    gemm_smemA<4>(As, Wo + 256 * H, Wb, C, wr, wc, gid, tig, tid);

#pragma unroll
    for (int mi = 0; mi < 2; ++mi)
#pragma unroll
        for (int ni = 0; ni < 4; ++ni) {
            const int col = wc + ni * 8 + 2 * tig;
            const float bx = bo[col], by = bo[col + 1];
#pragma unroll
            for (int half = 0; half < 2; ++half) {
                const int row = brow + wr + mi * 16 + gid + half * 8;
                if (row >= N) continue;
                float o0 = fmaxf(C[mi][ni][half*2+0] + bx, 0.f);
                float o1 = fmaxf(C[mi][ni][half*2+1] + by, 0.f);
                if (row == 0) { o0 = 0.f; o1 = 0.f; }
                *(float2*)&out[(size_t)row * H + col] = make_float2(o0, o1);
            }
        }
}

// ---------------------------------------------------------------------------
extern "C" void kernel_launch(void* const* d_in, const int* in_sizes, int n_in,
                              void* d_out, int out_size)
{
    const float* fnode  = (const float*) d_in[0];
    const float* fmess  = (const float*) d_in[1];
    const void*  agraph = d_in[2];
    const void*  bgraph = d_in[3];
    const float* Wz     = (const float*) d_in[4];
    const float* bz     = (const float*) d_in[5];
    const float* Wr     = (const float*) d_in[6];
    const float* Ur     = (const float*) d_in[7];
    const float* bur    = (const float*) d_in[8];
    const float* Wh     = (const float*) d_in[9];
    const float* bh     = (const float*) d_in[10];
    const float* Wo     = (const float*) d_in[11];
    const float* bo     = (const float*) d_in[12];

    const int N = in_sizes[2] / 6;
    const int E = in_sizes[3] / 6;

    float *Pz, *Pr, *Ph, *q1, *q2, *hA, *hB;
    int *bg32, *ag32;
    cudaGetSymbolAddress((void**)&Pz,   g_Pz);
    cudaGetSymbolAddress((void**)&Pr,   g_Pr);
    cudaGetSymbolAddress((void**)&Ph,   g_Ph);
    cudaGetSymbolAddress((void**)&q1,   g_q1);
    cudaGetSymbolAddress((void**)&q2,   g_q2);
    cudaGetSymbolAddress((void**)&hA,   g_hA);
    cudaGetSymbolAddress((void**)&hB,   g_hB);
    cudaGetSymbolAddress((void**)&bg32, g_bg32);
    cudaGetSymbolAddress((void**)&ag32, g_ag32);

    float* out_node = (float*)d_out;
    const long long need = (long long)(N + E) * H;
    const bool out_has_h = ((long long)out_size >= need);
    float* h_final = out_has_h ? ((float*)d_out + (size_t)N * H) : hA;

    detect_idx_kernel<<<1, 1>>>((const unsigned int*)bgraph);
    convert_idx_kernel<<<(E * 6 + 255) / 256, 256>>>(bgraph, bg32, E * 6);
    convert_idx_kernel<<<(N * 6 + 255) / 256, 256>>>(agraph, ag32, N * 6);

    const int gE128 = (E + 127) / 128;
    const int gE64  = (E + 63) / 64;
    const int gE32  = (E + 31) / 32;
    const int gN64  = (N + 63) / 64;

    // loop-invariant precompute (pipelined tensor-core GEMM, one launch):
    mm3_kernel<<<dim3(gE128, 3), 256>>>(fmess, 384, E, 384,
                                        Wz, Wr, Wh, bz, bur, bh, Pz, Pr, Ph);

    // iteration 1 (h=0): elementwise h + fused q = h@Ur
    fused_iter1_kernel<<<gE64, 256>>>(Pz, Ph, Ur, hA, q1, E);

    // iteration 2: gather + dual GEMM + GRU + fused q
    fused_gru_kernel<<<gE32, 256>>>(hA, q1, bg32, Pr, Pz, Ph,
                                    Wz + 384 * H, Wh + 384 * H, Ur, hB, q2, E, 1);

    // iteration 3: final h (no q needed)
    fused_gru_kernel<<<gE32, 256>>>(hB, q2, bg32, Pr, Pz, Ph,
                                    Wz + 384 * H, Wh + 384 * H, Ur, h_final, q1, E, 0);

    // output head: fused gather + dual-segment GEMM
    fused_node_kernel<<<gN64, 256>>>(fnode, Wo, h_final, ag32, bo, out_node, N);
}

// round 10
// speedup vs baseline: 1.6025x; 1.2117x over previous
#include <cuda_runtime.h>
#include <cuda_fp16.h>
#include <math.h>

#define H 128
#define E_MAX 80000
#define N_MAX 40000

// ---------------- scratch (device globals; no allocation allowed) ----------
__device__ __align__(16) float g_Pz [E_MAX * H];
__device__ __align__(16) float g_Pr [E_MAX * H];
__device__ __align__(16) float g_Ph [E_MAX * H];
__device__ __align__(16) float g_q1 [E_MAX * H];
__device__ __align__(16) float g_q2 [E_MAX * H];
__device__ __align__(16) float g_hA [E_MAX * H];
__device__ __align__(16) float g_hB [E_MAX * H];
__device__ int g_bg32[E_MAX * 6];
__device__ int g_ag32[N_MAX * 6];
__device__ int g_idx_is64;

__device__ __forceinline__ float sigmoidf_(float x) { return 1.0f / (1.0f + expf(-x)); }
__device__ __forceinline__ unsigned pk(float a, float b) {
    __half2 h = __floats2half2_rn(a, b);
    return *reinterpret_cast<unsigned*>(&h);
}

#define MMA_F16(C, A0,A1,A2,A3, B0,B1) \
    asm volatile("mma.sync.aligned.m16n8k16.row.col.f32.f16.f16.f32 " \
        "{%0,%1,%2,%3},{%4,%5,%6,%7},{%8,%9},{%0,%1,%2,%3};" \
        : "+f"((C)[0]), "+f"((C)[1]), "+f"((C)[2]), "+f"((C)[3]) \
        : "r"(A0), "r"(A1), "r"(A2), "r"(A3), "r"(B0), "r"(B1))

#define LDSM_X4(R0,R1,R2,R3,ADDR) \
    asm volatile("ldmatrix.sync.aligned.m8n8.x4.shared.b16 {%0,%1,%2,%3}, [%4];" \
        : "=r"(R0), "=r"(R1), "=r"(R2), "=r"(R3) : "r"(ADDR))

#define LDSM_X4_T(R0,R1,R2,R3,ADDR) \
    asm volatile("ldmatrix.sync.aligned.m8n8.x4.trans.shared.b16 {%0,%1,%2,%3}, [%4];" \
        : "=r"(R0), "=r"(R1), "=r"(R2), "=r"(R3) : "r"(ADDR))

// ---------------------------------------------------------------------------
// Index dtype normalize (JAX may ship int32 despite int64 in source).
// ---------------------------------------------------------------------------
__global__ void detect_idx_kernel(const unsigned int* __restrict__ w)
{
    g_idx_is64 = (w[1] == 0u && w[3] == 0u && w[5] == 0u && w[7] == 0u) ? 1 : 0;
}
__global__ void convert_idx_kernel(const void* __restrict__ src, int* __restrict__ dst, int n)
{
    int i = blockIdx.x * blockDim.x + threadIdx.x;
    if (i >= n) return;
    if (g_idx_is64) dst[i] = (int)((const long long*)src)[i];
    else            dst[i] = ((const int*)src)[i];
}

// ---------------------------------------------------------------------------
// fp16 GEMM helper: A resident in smem as halves [rows][136] (stride 272B),
// C += A[.., 0:128] @ W[0:128, 0:128].  Wb = [16][136] halves staging.
// Warp tile = 32 x (NT*8).  Fragments via ldmatrix (conflict-free strides).
// ---------------------------------------------------------------------------
template<int NT>
__device__ __forceinline__ void gemm_smemA_f16(
    unsigned AsB,                       // u32 smem addr of As[0][0]
    const float* __restrict__ W,        // gmem [128][128] fp32
    __half (*Wb)[136], unsigned WbB,
    float (&C)[2][NT][4],
    int wr, int wc, int lane, int tid)
{
    const int aRowOff = (wr + (lane & 15)) * 272 + ((lane >> 4) * 8) * 2;
    const int bAddr0  = ((lane & 7) + ((lane >> 3) & 1) * 8) * 272
                      + (wc + (lane >> 4) * 8) * 2;
    const int wrow = tid >> 4, wcb = (tid & 15) * 8;

    for (int k0 = 0; k0 < 128; k0 += 16) {
        // stage W chunk [16 x 128] fp32 -> half
        {
            const float* p = W + (size_t)(k0 + wrow) * H + wcb;
            const float4 v0 = *(const float4*)p, v1 = *(const float4*)(p + 4);
            uint4 w;
            w.x = pk(v0.x, v0.y); w.y = pk(v0.z, v0.w);
            w.z = pk(v1.x, v1.y); w.w = pk(v1.z, v1.w);
            *(uint4*)&Wb[wrow][wcb] = w;
        }
        __syncthreads();

        unsigned a[2][4];
#pragma unroll
        for (int mi = 0; mi < 2; ++mi)
            LDSM_X4(a[mi][0], a[mi][1], a[mi][2], a[mi][3],
                    AsB + aRowOff + mi * 16 * 272 + k0 * 2);
#pragma unroll
        for (int pr = 0; pr < NT / 2; ++pr) {
            unsigned b0, b1, b2, b3;
            LDSM_X4_T(b0, b1, b2, b3, WbB + bAddr0 + pr * 32);
            MMA_F16(C[0][2*pr],   a[0][0], a[0][1], a[0][2], a[0][3], b0, b1);
            MMA_F16(C[0][2*pr+1], a[0][0], a[0][1], a[0][2], a[0][3], b2, b3);
            MMA_F16(C[1][2*pr],   a[1][0], a[1][1], a[1][2], a[1][3], b0, b1);
            MMA_F16(C[1][2*pr+1], a[1][0], a[1][1], a[1][2], a[1][3], b2, b3);
        }
        __syncthreads();
    }
}

// ---------------------------------------------------------------------------
// mm3: out[y] = X @ W[y] + bias[y]   (fp16 MMA, BM=128, double-buffered)
// ---------------------------------------------------------------------------
__global__ void __launch_bounds__(256)
mm3_kernel(const float* __restrict__ X, int ldx, int M, int K,
           const float* __restrict__ W0, const float* __restrict__ W1, const float* __restrict__ W2,
           const float* __restrict__ b0, const float* __restrict__ b1, const float* __restrict__ b2,
           float* __restrict__ o0, float* __restrict__ o1, float* __restrict__ o2)
{
    __shared__ __align__(16) __half Xs[2][128][24];   // stride 48B, conflict-free ldsm
    __shared__ __align__(16) __half Ws[2][16][136];   // stride 272B

    const float* W   = (blockIdx.y == 0) ? W0 : (blockIdx.y == 1) ? W1 : W2;
    const float* bia = (blockIdx.y == 0) ? b0 : (blockIdx.y == 1) ? b1 : b2;
    float*       out = (blockIdx.y == 0) ? o0 : (blockIdx.y == 1) ? o1 : o2;

    const int tid = threadIdx.x, warp = tid >> 5, lane = tid & 31;
    const int gid = lane >> 2, tig = lane & 3;
    const int wr = (warp >> 1) * 32, wc = (warp & 1) * 64;
    const int brow = blockIdx.x * 128;

    const int xrow = tid >> 1, xcb = (tid & 1) * 8;
    const int wrow = tid >> 4, wcb = (tid & 15) * 8;
    const int xgr  = brow + xrow;

    const unsigned xs0 = (unsigned)__cvta_generic_to_shared(&Xs[0][0][0]);
    const unsigned ws0 = (unsigned)__cvta_generic_to_shared(&Ws[0][0][0]);
    const int aRowOff = (wr + (lane & 15)) * 48 + ((lane >> 4) * 8) * 2;
    const int bAddr0  = ((lane & 7) + ((lane >> 3) & 1) * 8) * 272
                      + (wc + (lane >> 4) * 8) * 2;

    float C[2][8][4];
#pragma unroll
    for (int i = 0; i < 2; ++i)
#pragma unroll
        for (int j = 0; j < 8; ++j)
#pragma unroll
            for (int k = 0; k < 4; ++k) C[i][j][k] = 0.f;

    float4 xv0, xv1, wv0, wv1;

    // prefetch chunk 0
    xv0 = make_float4(0.f,0.f,0.f,0.f); xv1 = xv0;
    if (xgr < M) {
        const float* p = X + (size_t)xgr * ldx + xcb;
        xv0 = *(const float4*)p; xv1 = *(const float4*)(p + 4);
    }
    {
        const float* wp = W + (size_t)wrow * H + wcb;
        wv0 = *(const float4*)wp; wv1 = *(const float4*)(wp + 4);
    }
    {
        uint4 xw; xw.x = pk(xv0.x,xv0.y); xw.y = pk(xv0.z,xv0.w);
                  xw.z = pk(xv1.x,xv1.y); xw.w = pk(xv1.z,xv1.w);
        *(uint4*)&Xs[0][xrow][xcb] = xw;
        uint4 ww; ww.x = pk(wv0.x,wv0.y); ww.y = pk(wv0.z,wv0.w);
                  ww.z = pk(wv1.x,wv1.y); ww.w = pk(wv1.z,wv1.w);
        *(uint4*)&Ws[0][wrow][wcb] = ww;
    }
    __syncthreads();

    const int nk = K >> 4;
    for (int it = 0; it < nk; ++it) {
        const int buf = it & 1;
        // LDG next chunk (latency hidden under compute)
        if (it + 1 < nk) {
            const int k0 = (it + 1) << 4;
            xv0 = make_float4(0.f,0.f,0.f,0.f); xv1 = xv0;
            if (xgr < M) {
                const float* p = X + (size_t)xgr * ldx + k0 + xcb;
                xv0 = *(const float4*)p; xv1 = *(const float4*)(p + 4);
            }
            const float* wp = W + (size_t)(k0 + wrow) * H + wcb;
            wv0 = *(const float4*)wp; wv1 = *(const float4*)(wp + 4);
        }
        // compute on buf
        {
            const unsigned xb = xs0 + buf * 6144;
            const unsigned wb = ws0 + buf * 4352;
            unsigned a[2][4];
#pragma unroll
            for (int mi = 0; mi < 2; ++mi)
                LDSM_X4(a[mi][0], a[mi][1], a[mi][2], a[mi][3],
                        xb + aRowOff + mi * 16 * 48);
#pragma unroll
            for (int pr = 0; pr < 4; ++pr) {
                unsigned bb0, bb1, bb2, bb3;
                LDSM_X4_T(bb0, bb1, bb2, bb3, wb + bAddr0 + pr * 32);
                MMA_F16(C[0][2*pr],   a[0][0], a[0][1], a[0][2], a[0][3], bb0, bb1);
                MMA_F16(C[0][2*pr+1], a[0][0], a[0][1], a[0][2], a[0][3], bb2, bb3);
                MMA_F16(C[1][2*pr],   a[1][0], a[1][1], a[1][2], a[1][3], bb0, bb1);
                MMA_F16(C[1][2*pr+1], a[1][0], a[1][1], a[1][2], a[1][3], bb2, bb3);
            }
        }
        // STS next chunk into other buffer
        if (it + 1 < nk) {
            const int nb = buf ^ 1;
            uint4 xw; xw.x = pk(xv0.x,xv0.y); xw.y = pk(xv0.z,xv0.w);
                      xw.z = pk(xv1.x,xv1.y); xw.w = pk(xv1.z,xv1.w);
            *(uint4*)&Xs[nb][xrow][xcb] = xw;
            uint4 ww; ww.x = pk(wv0.x,wv0.y); ww.y = pk(wv0.z,wv0.w);
                      ww.z = pk(wv1.x,wv1.y); ww.w = pk(wv1.z,wv1.w);
            *(uint4*)&Ws[nb][wrow][wcb] = ww;
        }
        __syncthreads();
    }

#pragma unroll
    for (int mi = 0; mi < 2; ++mi)
#pragma unroll
        for (int ni = 0; ni < 8; ++ni) {
            const int col = wc + ni * 8 + 2 * tig;
            const float bx = bia ? bia[col] : 0.f;
            const float by = bia ? bia[col + 1] : 0.f;
            const int r0 = brow + wr + mi * 16 + gid;
            const int r1 = r0 + 8;
            if (r0 < M) *(float2*)&out[(size_t)r0 * H + col] =
                make_float2(C[mi][ni][0] + bx, C[mi][ni][1] + by);
            if (r1 < M) *(float2*)&out[(size_t)r1 * H + col] =
                make_float2(C[mi][ni][2] + bx, C[mi][ni][3] + by);
        }
}

// ---------------------------------------------------------------------------
// fused_iter1: h = sigmoid(Pz)*tanh(Ph) -> global + smem(half); q = h @ Ur.
// BM=64, warps 2x4 (warp tile 32x32, NT=4).
// ---------------------------------------------------------------------------
__global__ void __launch_bounds__(256)
fused_iter1_kernel(const float* __restrict__ Pz, const float* __restrict__ Ph,
                   const float* __restrict__ Ur,
                   float* __restrict__ h_out, float* __restrict__ q_out, int E)
{
    __shared__ __align__(16) __half As[64][136];
    __shared__ __align__(16) __half Wb[16][136];

    const int tid = threadIdx.x, lane = tid & 31, ty = tid >> 5;
    const int gid = lane >> 2, tig = lane & 3;
    const int wr = (ty >> 2) * 32, wc = (ty & 3) * 32;
    const int brow = blockIdx.x * 64;
    const int c4 = lane * 4;

    const unsigned AsB = (unsigned)__cvta_generic_to_shared(&As[0][0]);
    const unsigned WbB = (unsigned)__cvta_generic_to_shared(&Wb[0][0]);

#pragma unroll
    for (int pass = 0; pass < 8; ++pass) {
        const int er = pass * 8 + ty;
        const int e  = brow + er;
        float4 v = make_float4(0.f,0.f,0.f,0.f);
        if (e < E) {
            const float4 pz = *(const float4*)&Pz[(size_t)e*H + c4];
            const float4 ph = *(const float4*)&Ph[(size_t)e*H + c4];
            v.x = sigmoidf_(pz.x) * tanhf(ph.x);
            v.y = sigmoidf_(pz.y) * tanhf(ph.y);
            v.z = sigmoidf_(pz.z) * tanhf(ph.z);
            v.w = sigmoidf_(pz.w) * tanhf(ph.w);
            if (e == 0) v = make_float4(0.f,0.f,0.f,0.f);
            *(float4*)&h_out[(size_t)e*H + c4] = v;
        }
        uint2 hv; hv.x = pk(v.x, v.y); hv.y = pk(v.z, v.w);
        *(uint2*)&As[er][c4] = hv;
    }
    __syncthreads();

    float C[2][4][4];
#pragma unroll
    for (int i = 0; i < 2; ++i)
#pragma unroll
        for (int j = 0; j < 4; ++j)
#pragma unroll
            for (int k = 0; k < 4; ++k) C[i][j][k] = 0.f;
    gemm_smemA_f16<4>(AsB, Ur, Wb, WbB, C, wr, wc, lane, tid);

#pragma unroll
    for (int mi = 0; mi < 2; ++mi)
#pragma unroll
        for (int ni = 0; ni < 4; ++ni) {
            const int col = wc + ni * 8 + 2 * tig;
            const int r0 = brow + wr + mi * 16 + gid;
            const int r1 = r0 + 8;
            if (r0 < E) *(float2*)&q_out[(size_t)r0 * H + col] =
                make_float2(C[mi][ni][0], C[mi][ni][1]);
            if (r1 < E) *(float2*)&q_out[(size_t)r1 * H + col] =
                make_float2(C[mi][ni][2], C[mi][ni][3]);
        }
}

// ---------------------------------------------------------------------------
// fused_gru: BM=32, warps 1x8 (warp tile 32x16, NT=2).
// gather(sh,sg) -> smem(half); Cz=sh@Wz2, Ch=sg@Wh2; GRU epilogue -> h_out +
// smem(half); optional q_out = h_new @ Ur.
// ---------------------------------------------------------------------------
__global__ void __launch_bounds__(256)
fused_gru_kernel(const float* __restrict__ h_in, const float* __restrict__ q_in,
                 const int* __restrict__ bg,
                 const float* __restrict__ Pr, const float* __restrict__ Pz,
                 const float* __restrict__ Ph,
                 const float* __restrict__ Wz2, const float* __restrict__ Wh2,
                 const float* __restrict__ Ur,
                 float* __restrict__ h_out, float* __restrict__ q_out,
                 int E, int do_q)
{
    __shared__ __align__(16) __half SHs[32][136];
    __shared__ __align__(16) __half SGs[32][136];
    __shared__ __align__(16) __half Wb[16][136];

    const int tid = threadIdx.x, lane = tid & 31, ty = tid >> 5;
    const int gid = lane >> 2, tig = lane & 3;
    const int wc = ty * 16;
    const int brow = blockIdx.x * 32;
    const int c4 = lane * 4;

    const unsigned SHB = (unsigned)__cvta_generic_to_shared(&SHs[0][0]);
    const unsigned SGB = (unsigned)__cvta_generic_to_shared(&SGs[0][0]);
    const unsigned WbB = (unsigned)__cvta_generic_to_shared(&Wb[0][0]);

#pragma unroll
    for (int pass = 0; pass < 4; ++pass) {
        const int er = pass * 8 + ty;
        const int e  = brow + er;
        float4 sh = make_float4(0.f,0.f,0.f,0.f);
        float4 sg = make_float4(0.f,0.f,0.f,0.f);
        if (e < E) {
            const float4 pr = *(const float4*)&Pr[(size_t)e*H + c4];
#pragma unroll
            for (int j = 0; j < 6; ++j) {
                const int idx = __ldg(&bg[e * 6 + j]);
                const float4 hn = *(const float4*)&h_in[(size_t)idx*H + c4];
                const float4 qn = *(const float4*)&q_in[(size_t)idx*H + c4];
                sh.x += hn.x; sh.y += hn.y; sh.z += hn.z; sh.w += hn.w;
                sg.x += hn.x * sigmoidf_(pr.x + qn.x);
                sg.y += hn.y * sigmoidf_(pr.y + qn.y);
                sg.z += hn.z * sigmoidf_(pr.z + qn.z);
                sg.w += hn.w * sigmoidf_(pr.w + qn.w);
            }
        }
        uint2 a; a.x = pk(sh.x, sh.y); a.y = pk(sh.z, sh.w);
        *(uint2*)&SHs[er][c4] = a;
        uint2 b; b.x = pk(sg.x, sg.y); b.y = pk(sg.z, sg.w);
        *(uint2*)&SGs[er][c4] = b;
    }

    float Cz[2][2][4], Ch[2][2][4];
#pragma unroll
    for (int i = 0; i < 2; ++i)
#pragma unroll
        for (int j = 0; j < 2; ++j)
#pragma unroll
            for (int k = 0; k < 4; ++k) { Cz[i][j][k] = 0.f; Ch[i][j][k] = 0.f; }

    gemm_smemA_f16<2>(SHB, Wz2, Wb, WbB, Cz, 0, wc, lane, tid);
    gemm_smemA_f16<2>(SGB, Wh2, Wb, WbB, Ch, 0, wc, lane, tid);

#pragma unroll
    for (int mi = 0; mi < 2; ++mi)
#pragma unroll
        for (int ni = 0; ni < 2; ++ni) {
            const int col = wc + ni * 8 + 2 * tig;
#pragma unroll
            for (int half = 0; half < 2; ++half) {
                const int lr  = mi * 16 + gid + half * 8;
                const int row = brow + lr;
                if (row >= E) continue;
                const size_t base = (size_t)row * H + col;
                const float2 pz = *(const float2*)&Pz[base];
                const float2 ph = *(const float2*)&Ph[base];
                const float sh0 = __half2float(SHs[lr][col]);
                const float sh1 = __half2float(SHs[lr][col + 1]);
                const float z0 = sigmoidf_(Cz[mi][ni][half*2+0] + pz.x);
                const float z1 = sigmoidf_(Cz[mi][ni][half*2+1] + pz.y);
                const float p0 = tanhf(Ch[mi][ni][half*2+0] + ph.x);
                const float p1 = tanhf(Ch[mi][ni][half*2+1] + ph.y);
                float o0 = (1.f - z0) * sh0 + z0 * p0;
                float o1 = (1.f - z1) * sh1 + z1 * p1;
                if (row == 0) { o0 = 0.f; o1 = 0.f; }
                *(float2*)&h_out[base] = make_float2(o0, o1);
                *(unsigned*)&SHs[lr][col] = pk(o0, o1);
            }
        }
    if (!do_q) return;
    __syncthreads();

    float Cq[2][2][4];
#pragma unroll
    for (int i = 0; i < 2; ++i)
#pragma unroll
        for (int j = 0; j < 2; ++j)
#pragma unroll
            for (int k = 0; k < 4; ++k) Cq[i][j][k] = 0.f;
    gemm_smemA_f16<2>(SHB, Ur, Wb, WbB, Cq, 0, wc, lane, tid);

#pragma unroll
    for (int mi = 0; mi < 2; ++mi)
#pragma unroll
        for (int ni = 0; ni < 2; ++ni) {
            const int col = wc + ni * 8 + 2 * tig;
            const int r0 = brow + mi * 16 + gid;
            const int r1 = r0 + 8;
            if (r0 < E) *(float2*)&q_out[(size_t)r0 * H + col] =
                make_float2(Cq[mi][ni][0], Cq[mi][ni][1]);
            if (r1 < E) *(float2*)&q_out[(size_t)r1 * H + col] =
                make_float2(Cq[mi][ni][2], Cq[mi][ni][3]);
        }
}

// ---------------------------------------------------------------------------
// fused_node: BM=64, warps 2x4 (NT=4).
// C = fnode @ Wo[0:256] + gather(nei) @ Wo[256:384]; relu(+bo), row0 mask.
// ---------------------------------------------------------------------------
__global__ void __launch_bounds__(256)
fused_node_kernel(const float* __restrict__ fnode, const float* __restrict__ Wo,
                  const float* __restrict__ h, const int* __restrict__ ag,
                  const float* __restrict__ bo, float* __restrict__ out, int N)
{
    __shared__ __align__(16) __half As[64][136];
    __shared__ __align__(16) __half Wb[16][136];

    const int tid = threadIdx.x, lane = tid & 31, ty = tid >> 5;
    const int gid = lane >> 2, tig = lane & 3;
    const int wr = (ty >> 2) * 32, wc = (ty & 3) * 32;
    const int brow = blockIdx.x * 64;
    const int c4 = lane * 4;

    const unsigned AsB = (unsigned)__cvta_generic_to_shared(&As[0][0]);
    const unsigned WbB = (unsigned)__cvta_generic_to_shared(&Wb[0][0]);
    const int aRowOff = (wr + (lane & 15)) * 272 + ((lane >> 4) * 8) * 2;
    const int bAddr0  = ((lane & 7) + ((lane >> 3) & 1) * 8) * 272
                      + (wc + (lane >> 4) * 8) * 2;
    const int wrow = tid >> 4, wcb = (tid & 15) * 8;

    float C[2][4][4];
#pragma unroll
    for (int i = 0; i < 2; ++i)
#pragma unroll
        for (int j = 0; j < 4; ++j)
#pragma unroll
            for (int k = 0; k < 4; ++k) C[i][j][k] = 0.f;

    // phase A: fnode @ Wo[0:256], per-chunk staging into As cols [0,16)
    for (int k0 = 0; k0 < 256; k0 += 16) {
        {
            const int row = tid >> 2, cb = (tid & 3) * 4;
            const int gr  = brow + row;
            float4 v = make_float4(0.f,0.f,0.f,0.f);
            if (gr < N) v = *(const float4*)&fnode[(size_t)gr * 256 + k0 + cb];
            uint2 hv; hv.x = pk(v.x, v.y); hv.y = pk(v.z, v.w);
            *(uint2*)&As[row][cb] = hv;
        }
        {
            const float* p = Wo + (size_t)(k0 + wrow) * H + wcb;
            const float4 v0 = *(const float4*)p, v1 = *(const float4*)(p + 4);
            uint4 w;
            w.x = pk(v0.x, v0.y); w.y = pk(v0.z, v0.w);
            w.z = pk(v1.x, v1.y); w.w = pk(v1.z, v1.w);
            *(uint4*)&Wb[wrow][wcb] = w;
        }
        __syncthreads();
        unsigned a[2][4];
#pragma unroll
        for (int mi = 0; mi < 2; ++mi)
            LDSM_X4(a[mi][0], a[mi][1], a[mi][2], a[mi][3],
                    AsB + aRowOff + mi * 16 * 272);
#pragma unroll
        for (int pr = 0; pr < 2; ++pr) {
            unsigned bb0, bb1, bb2, bb3;
            LDSM_X4_T(bb0, bb1, bb2, bb3, WbB + bAddr0 + pr * 32);
            MMA_F16(C[0][2*pr],   a[0][0], a[0][1], a[0][2], a[0][3], bb0, bb1);
            MMA_F16(C[0][2*pr+1], a[0][0], a[0][1], a[0][2], a[0][3], bb2, bb3);
            MMA_F16(C[1][2*pr],   a[1][0], a[1][1], a[1][2], a[1][3], bb0, bb1);
            MMA_F16(C[1][2*pr+1], a[1][0], a[1][1], a[1][2], a[1][3], bb2, bb3);
        }
        __syncthreads();
    }

    // phase B: gather nei into As (full width, half)
#pragma unroll
    for (int pass = 0; pass < 8; ++pass) {
        const int nr = pass * 8 + ty;
        const int n  = brow + nr;
        float4 s = make_float4(0.f,0.f,0.f,0.f);
        if (n < N) {
#pragma unroll
            for (int j = 0; j < 6; ++j) {
                const int idx = __ldg(&ag[n * 6 + j]);
                const float4 hn = *(const float4*)&h[(size_t)idx*H + c4];
                s.x += hn.x; s.y += hn.y; s.z += hn.z; s.w += hn.w;
            }
        }
        uint2 hv; hv.x = pk(s.x, s.y); hv.y = pk(s.z, s.w);
        *(uint2*)&As[nr][c4] = hv;
    }
    __syncthreads();

    gemm_smemA_f16<4>(AsB, Wo + 256 * H, Wb, WbB, C, wr, wc, lane, tid);

#pragma unroll
    for (int mi = 0; mi < 2; ++mi)
#pragma unroll
        for (int ni = 0; ni < 4; ++ni) {
            const int col = wc + ni * 8 + 2 * tig;
            const float bx = bo[col], by = bo[col + 1];
#pragma unroll
            for (int half = 0; half < 2; ++half) {
                const int row = brow + wr + mi * 16 + gid + half * 8;
                if (row >= N) continue;
                float o0 = fmaxf(C[mi][ni][half*2+0] + bx, 0.f);
                float o1 = fmaxf(C[mi][ni][half*2+1] + by, 0.f);
                if (row == 0) { o0 = 0.f; o1 = 0.f; }
                *(float2*)&out[(size_t)row * H + col] = make_float2(o0, o1);
            }
        }
}

// ---------------------------------------------------------------------------
extern "C" void kernel_launch(void* const* d_in, const int* in_sizes, int n_in,
                              void* d_out, int out_size)
{
    const float* fnode  = (const float*) d_in[0];
    const float* fmess  = (const float*) d_in[1];
    const void*  agraph = d_in[2];
    const void*  bgraph = d_in[3];
    const float* Wz     = (const float*) d_in[4];
    const float* bz     = (const float*) d_in[5];
    const float* Wr     = (const float*) d_in[6];
    const float* Ur     = (const float*) d_in[7];
    const float* bur    = (const float*) d_in[8];
    const float* Wh     = (const float*) d_in[9];
    const float* bh     = (const float*) d_in[10];
    const float* Wo     = (const float*) d_in[11];
    const float* bo     = (const float*) d_in[12];

    const int N = in_sizes[2] / 6;
    const int E = in_sizes[3] / 6;

    float *Pz, *Pr, *Ph, *q1, *q2, *hA, *hB;
    int *bg32, *ag32;
    cudaGetSymbolAddress((void**)&Pz,   g_Pz);
    cudaGetSymbolAddress((void**)&Pr,   g_Pr);
    cudaGetSymbolAddress((void**)&Ph,   g_Ph);
    cudaGetSymbolAddress((void**)&q1,   g_q1);
    cudaGetSymbolAddress((void**)&q2,   g_q2);
    cudaGetSymbolAddress((void**)&hA,   g_hA);
    cudaGetSymbolAddress((void**)&hB,   g_hB);
    cudaGetSymbolAddress((void**)&bg32, g_bg32);
    cudaGetSymbolAddress((void**)&ag32, g_ag32);

    float* out_node = (float*)d_out;
    const long long need = (long long)(N + E) * H;
    const bool out_has_h = ((long long)out_size >= need);
    float* h_final = out_has_h ? ((float*)d_out + (size_t)N * H) : hA;

    detect_idx_kernel<<<1, 1>>>((const unsigned int*)bgraph);
    convert_idx_kernel<<<(E * 6 + 255) / 256, 256>>>(bgraph, bg32, E * 6);
    convert_idx_kernel<<<(N * 6 + 255) / 256, 256>>>(agraph, ag32, N * 6);

    const int gE128 = (E + 127) / 128;
    const int gE64  = (E + 63) / 64;
    const int gE32  = (E + 31) / 32;
    const int gN64  = (N + 63) / 64;

    // loop-invariant precompute (fp16 tensor cores, one launch):
    mm3_kernel<<<dim3(gE128, 3), 256>>>(fmess, 384, E, 384,
                                        Wz, Wr, Wh, bz, bur, bh, Pz, Pr, Ph);

    // iteration 1 (h=0): elementwise h + fused q = h@Ur
    fused_iter1_kernel<<<gE64, 256>>>(Pz, Ph, Ur, hA, q1, E);

    // iteration 2: gather + dual GEMM + GRU + fused q
    fused_gru_kernel<<<gE32, 256>>>(hA, q1, bg32, Pr, Pz, Ph,
                                    Wz + 384 * H, Wh + 384 * H, Ur, hB, q2, E, 1);

    // iteration 3: final h (no q needed)
    fused_gru_kernel<<<gE32, 256>>>(hB, q2, bg32, Pr, Pz, Ph,
                                    Wz + 384 * H, Wh + 384 * H, Ur, h_final, q1, E, 0);

    // output head: fused gather + dual-segment GEMM
    fused_node_kernel<<<gN64, 256>>>(fnode, Wo, h_final, ag32, bo, out_node, N);
}